// round 2
// baseline (speedup 1.0000x reference)
#include <cuda_runtime.h>
#include <cuda_bf16.h>
#include <math.h>

// Dimensions (fixed by the problem)
#define B_ROWS 512
#define D_IN 5
#define H_DIM 128
#define VF_DIM 256
#define L_SEG 62        // LS-1
#define LAB 10
#define NSTEP 20
#define RB 4            // rows per CTA
#define NCTA (B_ROWS / RB)   // 128
#define NTHR 256

// Precomputed global scratch (device globals: no allocation allowed)
__device__ float g_W1t[H_DIM * VF_DIM];          // [k=128][c=256]  (W_vf1 transposed)
__device__ float g_W2t[VF_DIM * VF_DIM];         // [k=256][c=256]  (W_vf2 transposed)
__device__ float g_Wm[32 * VF_DIM * H_DIM];      // [idx][v=256][h=128]  4 MB
__device__ float g_bm[32 * H_DIM];               // [idx][h]
__device__ float g_delta[32];                    // interval widths
__device__ int   g_idx[2 * NSTEP];               // 0-based logsig row per eval

// ---------------------------------------------------------------------------
// Kernel 1: transposes + interval index / delta precompute
// ---------------------------------------------------------------------------
__global__ void prep_kernel(const float* __restrict__ ts,
                            const float* __restrict__ intervals,
                            const float* __restrict__ W1,   // [256][128]
                            const float* __restrict__ W2)   // [256][256]
{
    int gtid = blockIdx.x * blockDim.x + threadIdx.x;
    int gsz  = gridDim.x * blockDim.x;

    for (int i = gtid; i < H_DIM * VF_DIM; i += gsz) {
        int k = i >> 8, c = i & 255;
        g_W1t[i] = W1[c * H_DIM + k];
    }
    for (int i = gtid; i < VF_DIM * VF_DIM; i += gsz) {
        int k = i >> 8, c = i & 255;
        g_W2t[i] = W2[c * VF_DIM + k];
    }
    if (gtid < 32) {
        g_delta[gtid] = intervals[gtid + 1] - intervals[gtid];
    }
    if (gtid < 2 * NSTEP) {
        // Replicate reference fp32 exactly: dt = (t1-t0)/20 ; t = t0 + i*dt ; k2 uses t+dt
        float t0 = ts[0];
        float dt = (ts[32] - t0) / 20.0f;
        int i = gtid >> 1;
        float t = t0 + (float)i * dt;
        if (gtid & 1) t = t + dt;
        int cnt = 0;
        #pragma unroll
        for (int j = 1; j <= 32; j++) cnt += (intervals[j] < t) ? 1 : 0;
        int idx = cnt + 1;
        idx = max(1, min(idx, 32));
        g_idx[gtid] = idx - 1;
    }
}

// ---------------------------------------------------------------------------
// Kernel 2: fold logsig into W_m  ->  Wm_eff[idx][v][h], bm_eff[idx][h]
// grid = 128 (h), block = 256 (v)
// ---------------------------------------------------------------------------
__global__ void __launch_bounds__(256) wmeff_kernel(const float* __restrict__ logsig,  // [32][63]
                                                    const float* __restrict__ Wm,      // [7936][256]
                                                    const float* __restrict__ bm)      // [7936]
{
    __shared__ float ls[32 * L_SEG];
    int h = blockIdx.x;
    int v = threadIdx.x;

    for (int i = threadIdx.x; i < 32 * L_SEG; i += blockDim.x) {
        int row = i / L_SEG, l = i % L_SEG;
        ls[i] = logsig[row * 63 + l + 1];
    }
    __syncthreads();

    float acc[32];
    #pragma unroll
    for (int i = 0; i < 32; i++) acc[i] = 0.0f;

    for (int l = 0; l < L_SEG; l++) {
        float w = __ldg(&Wm[(h * L_SEG + l) * VF_DIM + v]);
        #pragma unroll
        for (int i = 0; i < 32; i++) acc[i] += w * ls[i * L_SEG + l];
    }
    #pragma unroll
    for (int i = 0; i < 32; i++)
        g_Wm[i * (VF_DIM * H_DIM) + v * H_DIM + h] = acc[i];

    if (threadIdx.x < 32) {
        int i = threadIdx.x;
        float s = 0.0f;
        for (int l = 0; l < L_SEG; l++)
            s += __ldg(&bm[h * L_SEG + l]) * ls[i * L_SEG + l];
        g_bm[i * H_DIM + h] = s;
    }
}

// ---------------------------------------------------------------------------
// Kernel 3: persistent integration. 128 CTAs x 256 threads, 4 rows per CTA.
// State (y) lives in shared memory for the entire 20-step Heun solve.
// ---------------------------------------------------------------------------
#define SMEM_FLOATS (H_DIM * VF_DIM + 512 + 512 + 512 + 1024 + 1024)

__global__ void __launch_bounds__(256, 1)
integrate_kernel(const float* __restrict__ x0,     // [512][5]
                 const float* __restrict__ W_in,   // [128][5]
                 const float* __restrict__ b_in,   // [128]
                 const float* __restrict__ b1,     // [256]
                 const float* __restrict__ b2,     // [256]
                 const float* __restrict__ W_out,  // [10][128]
                 const float* __restrict__ b_out,  // [10]
                 const float* __restrict__ ts,
                 float* __restrict__ out)          // [512][10]
{
    extern __shared__ float sm[];
    float* W1s  = sm;                       // 32768 : W1t cached [k][c]
    float* y_s  = W1s + H_DIM * VF_DIM;     // 512   : y   [k=128][r=4]
    float* yt_s = y_s + 512;                // 512   : y + dt*k1
    float* k1_s = yt_s + 512;               // 512   : k1
    float* h1_s = k1_s + 512;               // 1024  : layer1 act [v=256][r=4] (also reduce scratch)
    float* h2_s = h1_s + 1024;              // 1024  : layer2 act

    const int tid = threadIdx.x;
    const int r0  = blockIdx.x * RB;

    // Cache W1t into shared memory
    for (int i = tid; i < H_DIM * VF_DIM; i += NTHR) W1s[i] = g_W1t[i];

    // y0 = x0 @ W_in^T + b_in   (512 outputs for this CTA, 2 per thread)
    {
        int h  = tid & 127;
        int rb = (tid >> 7) * 2;
        #pragma unroll
        for (int rr = 0; rr < 2; rr++) {
            int r = rb + rr;
            float acc = __ldg(&b_in[h]);
            #pragma unroll
            for (int d = 0; d < D_IN; d++)
                acc += __ldg(&x0[(r0 + r) * D_IN + d]) * __ldg(&W_in[h * D_IN + d]);
            y_s[h * RB + r] = acc;
        }
    }
    const float dt = (ts[32] - ts[0]) / 20.0f;
    __syncthreads();

    const int c = tid;

    for (int step = 0; step < NSTEP; step++) {
        #pragma unroll 1
        for (int phase = 0; phase < 2; phase++) {
            const float* in_s = phase ? yt_s : y_s;
            const int kt = g_idx[2 * step + phase];

            // ---- Layer 1: h1 = relu(y @ W1^T + b1), K=128, 256 cols ----
            float a0, a1, a2, a3;
            {
                float bb = __ldg(&b1[c]);
                a0 = bb; a1 = bb; a2 = bb; a3 = bb;
                #pragma unroll 8
                for (int k = 0; k < H_DIM; k++) {
                    float w = W1s[k * VF_DIM + c];
                    float4 yv = *(const float4*)&in_s[k * RB];
                    a0 += yv.x * w; a1 += yv.y * w; a2 += yv.z * w; a3 += yv.w * w;
                }
                float4 hv = make_float4(fmaxf(a0, 0.f), fmaxf(a1, 0.f),
                                        fmaxf(a2, 0.f), fmaxf(a3, 0.f));
                *(float4*)&h1_s[c * RB] = hv;
            }
            __syncthreads();

            // ---- Layer 2: h2 = tanh(h1 @ W2^T + b2), K=256, 256 cols ----
            {
                float bb = __ldg(&b2[c]);
                a0 = bb; a1 = bb; a2 = bb; a3 = bb;
                #pragma unroll 8
                for (int k = 0; k < VF_DIM; k++) {
                    float w = __ldg(&g_W2t[k * VF_DIM + c]);
                    float4 yv = *(const float4*)&h1_s[k * RB];
                    a0 += yv.x * w; a1 += yv.y * w; a2 += yv.z * w; a3 += yv.w * w;
                }
                *(float4*)&h2_s[c * RB] =
                    make_float4(tanhf(a0), tanhf(a1), tanhf(a2), tanhf(a3));
            }
            __syncthreads();

            // ---- Layer 3: dydt = (h2 @ Wm_eff^T + bm_eff) / delta, 128 cols, split-K x2 ----
            {
                int h  = tid & 127;
                int hp = tid >> 7;   // K-half
                const float* Wp = &g_Wm[kt * (VF_DIM * H_DIM) + hp * (128 * H_DIM) + h];
                a0 = 0.f; a1 = 0.f; a2 = 0.f; a3 = 0.f;
                #pragma unroll 8
                for (int k = 0; k < 128; k++) {
                    float w = __ldg(&Wp[k * H_DIM]);
                    float4 yv = *(const float4*)&h2_s[(hp * 128 + k) * RB];
                    a0 += yv.x * w; a1 += yv.y * w; a2 += yv.z * w; a3 += yv.w * w;
                }
                if (hp) { *(float4*)&h1_s[h * RB] = make_float4(a0, a1, a2, a3); }
                __syncthreads();
                if (!hp) {
                    float4 p = *(const float4*)&h1_s[h * RB];
                    float dl = g_delta[kt];
                    float bm = g_bm[kt * H_DIM + h];
                    float d0 = (a0 + p.x + bm) / dl;
                    float d1 = (a1 + p.y + bm) / dl;
                    float d2 = (a2 + p.z + bm) / dl;
                    float d3 = (a3 + p.w + bm) / dl;
                    int base = h * RB;
                    if (phase == 0) {
                        k1_s[base + 0] = d0; k1_s[base + 1] = d1;
                        k1_s[base + 2] = d2; k1_s[base + 3] = d3;
                        yt_s[base + 0] = y_s[base + 0] + dt * d0;
                        yt_s[base + 1] = y_s[base + 1] + dt * d1;
                        yt_s[base + 2] = y_s[base + 2] + dt * d2;
                        yt_s[base + 3] = y_s[base + 3] + dt * d3;
                    } else {
                        y_s[base + 0] = y_s[base + 0] + 0.5f * dt * (k1_s[base + 0] + d0);
                        y_s[base + 1] = y_s[base + 1] + 0.5f * dt * (k1_s[base + 1] + d1);
                        y_s[base + 2] = y_s[base + 2] + 0.5f * dt * (k1_s[base + 2] + d2);
                        y_s[base + 3] = y_s[base + 3] + 0.5f * dt * (k1_s[base + 3] + d3);
                    }
                }
                __syncthreads();
            }
        }
    }

    // ---- Output: softmax(y @ W_out^T + b_out), 4 rows x 10 labels ----
    if (tid < RB * LAB) {
        int lab = tid % LAB, r = tid / LAB;
        float acc = __ldg(&b_out[lab]);
        for (int k = 0; k < H_DIM; k++)
            acc += y_s[k * RB + r] * __ldg(&W_out[lab * H_DIM + k]);
        h1_s[r * LAB + lab] = acc;
    }
    __syncthreads();
    if (tid < RB) {
        int r = tid;
        float mx = -1e30f;
        #pragma unroll
        for (int l = 0; l < LAB; l++) mx = fmaxf(mx, h1_s[r * LAB + l]);
        float e[LAB]; float s = 0.f;
        #pragma unroll
        for (int l = 0; l < LAB; l++) { e[l] = expf(h1_s[r * LAB + l] - mx); s += e[l]; }
        #pragma unroll
        for (int l = 0; l < LAB; l++) out[(r0 + r) * LAB + l] = e[l] / s;
    }
}

// ---------------------------------------------------------------------------
extern "C" void kernel_launch(void* const* d_in, const int* in_sizes, int n_in,
                              void* d_out, int out_size)
{
    const float* ts        = (const float*)d_in[0];
    const float* logsig    = (const float*)d_in[1];
    const float* x0        = (const float*)d_in[2];
    const float* intervals = (const float*)d_in[3];
    const float* W_vf1     = (const float*)d_in[4];
    const float* b_vf1     = (const float*)d_in[5];
    const float* W_vf2     = (const float*)d_in[6];
    const float* b_vf2     = (const float*)d_in[7];
    const float* W_m       = (const float*)d_in[8];
    const float* b_m       = (const float*)d_in[9];
    const float* W_in      = (const float*)d_in[10];
    const float* b_in      = (const float*)d_in[11];
    const float* W_out     = (const float*)d_in[12];
    const float* b_out     = (const float*)d_in[13];
    float* out = (float*)d_out;

    size_t smem_bytes = SMEM_FLOATS * sizeof(float);  // 145408 B
    cudaFuncSetAttribute(integrate_kernel,
                         cudaFuncAttributeMaxDynamicSharedMemorySize,
                         (int)smem_bytes);

    prep_kernel<<<64, 256>>>(ts, intervals, W_vf1, W_vf2);
    wmeff_kernel<<<128, 256>>>(logsig, W_m, b_m);
    integrate_kernel<<<NCTA, NTHR, smem_bytes>>>(x0, W_in, b_in, b_vf1, b_vf2,
                                                 W_out, b_out, ts, out);
}

// round 6
// speedup vs baseline: 2.6453x; 2.6453x over previous
#include <cuda_runtime.h>
#include <cuda_bf16.h>
#include <math.h>

// Dimensions (fixed by the problem)
#define B_ROWS 512
#define D_IN 5
#define H_DIM 128
#define VF_DIM 256
#define L_SEG 62        // LS-1
#define LAB 10
#define NSTEP 20
#define RB 4            // rows per CTA
#define NCTA (B_ROWS / RB)   // 128
#define NTHR 512

// Precomputed global scratch (device globals: no allocation allowed)
__device__ float g_W1t[H_DIM * VF_DIM];          // [k=128][c=256]
__device__ float g_W2t[VF_DIM * VF_DIM];         // [k=256][c=256]
__device__ float g_Wm[32 * VF_DIM * H_DIM];      // [idx][v=256][h=128]  4 MB
__device__ float g_bm[32 * H_DIM];               // [idx][h]
__device__ float g_delta[32];                    // interval widths
__device__ int   g_idx[2 * NSTEP];               // 0-based logsig row per eval

// ---------------------------------------------------------------------------
// f32x2 packed-FMA helpers (sm_103a FFMA2 — PTX-only)
// ---------------------------------------------------------------------------
__device__ __forceinline__ unsigned long long dup2(float x) {
    unsigned long long r;
    unsigned int u = __float_as_uint(x);
    asm("mov.b64 %0, {%1, %1};" : "=l"(r) : "r"(u));
    return r;
}
__device__ __forceinline__ void fma2(unsigned long long& acc,
                                     unsigned long long a, unsigned long long b) {
    asm("fma.rn.f32x2 %0, %1, %2, %0;" : "+l"(acc) : "l"(a), "l"(b));
}
__device__ __forceinline__ void unpk(unsigned long long v, float& a, float& b) {
    unsigned int lo, hi;
    asm("mov.b64 {%0, %1}, %2;" : "=r"(lo), "=r"(hi) : "l"(v));
    a = __uint_as_float(lo);
    b = __uint_as_float(hi);
}

// ---------------------------------------------------------------------------
// Setup kernel (merged prep + wmeff).  grid = 160 x 256.
//   blocks [0,128): fold logsig into W_m  -> g_Wm / g_bm  (h = blockIdx.x)
//   blocks [128,160): transposes + interval index / delta precompute
// ---------------------------------------------------------------------------
__global__ void __launch_bounds__(256) setup_kernel(
    const float* __restrict__ ts,
    const float* __restrict__ intervals,
    const float* __restrict__ W1,      // [256][128]
    const float* __restrict__ W2,      // [256][256]
    const float* __restrict__ logsig,  // [32][63]
    const float* __restrict__ Wm,      // [7936][256]
    const float* __restrict__ bm)      // [7936]
{
    if (blockIdx.x < 128) {
        __shared__ float ls[32 * L_SEG];
        int h = blockIdx.x;
        int v = threadIdx.x;

        for (int i = threadIdx.x; i < 32 * L_SEG; i += blockDim.x) {
            int row = i / L_SEG, l = i % L_SEG;
            ls[i] = logsig[row * 63 + l + 1];
        }
        __syncthreads();

        float acc[32];
        #pragma unroll
        for (int i = 0; i < 32; i++) acc[i] = 0.0f;

        for (int l = 0; l < L_SEG; l++) {
            float w = __ldg(&Wm[(h * L_SEG + l) * VF_DIM + v]);
            #pragma unroll
            for (int i = 0; i < 32; i++) acc[i] += w * ls[i * L_SEG + l];
        }
        #pragma unroll
        for (int i = 0; i < 32; i++)
            g_Wm[i * (VF_DIM * H_DIM) + v * H_DIM + h] = acc[i];

        if (threadIdx.x < 32) {
            int i = threadIdx.x;
            float s = 0.0f;
            for (int l = 0; l < L_SEG; l++)
                s += __ldg(&bm[h * L_SEG + l]) * ls[i * L_SEG + l];
            g_bm[i * H_DIM + h] = s;
        }
    } else {
        int b = blockIdx.x - 128;              // 0..31
        int gtid = b * 256 + threadIdx.x;      // 0..8191
        int gsz  = 32 * 256;

        for (int i = gtid; i < H_DIM * VF_DIM; i += gsz) {
            int k = i >> 8, c = i & 255;
            g_W1t[i] = W1[c * H_DIM + k];
        }
        for (int i = gtid; i < VF_DIM * VF_DIM; i += gsz) {
            int k = i >> 8, c = i & 255;
            g_W2t[i] = W2[c * VF_DIM + k];
        }
        if (b == 0) {
            if (threadIdx.x < 32)
                g_delta[threadIdx.x] = intervals[threadIdx.x + 1] - intervals[threadIdx.x];
            if (threadIdx.x < 2 * NSTEP) {
                // Replicate reference fp32 exactly
                float t0 = ts[0];
                float dt = (ts[32] - t0) / 20.0f;
                int i = threadIdx.x >> 1;
                float t = t0 + (float)i * dt;
                if (threadIdx.x & 1) t = t + dt;
                int cnt = 0;
                #pragma unroll
                for (int j = 1; j <= 32; j++) cnt += (intervals[j] < t) ? 1 : 0;
                int idx = cnt + 1;
                idx = max(1, min(idx, 32));
                g_idx[threadIdx.x] = idx - 1;
            }
        }
    }
}

// ---------------------------------------------------------------------------
// Persistent integration kernel: 128 CTAs x 512 threads, 4 rows per CTA.
// 4col x 4row register blocking, f32x2 packed FMA, split-K with smem reduce.
// ---------------------------------------------------------------------------
#define SMEM_FLOATS (32768 + 512 + 512 + 512 + 1024 + 1024 + 8192)  // 44544 = 178 KB

__global__ void __launch_bounds__(NTHR, 1)
integrate_kernel(const float* __restrict__ x0,     // [512][5]
                 const float* __restrict__ W_in,   // [128][5]
                 const float* __restrict__ b_in,   // [128]
                 const float* __restrict__ b1,     // [256]
                 const float* __restrict__ b2,     // [256]
                 const float* __restrict__ W_out,  // [10][128]
                 const float* __restrict__ b_out,  // [10]
                 const float* __restrict__ ts,
                 float* __restrict__ out)          // [512][10]
{
    extern __shared__ __align__(16) float sm[];
    float* W1s  = sm;                    // 32768 : W1t cached [k][c]
    float* y_s  = W1s + 32768;           // 512   : y   [h=128][r=4]
    float* yt_s = y_s + 512;             // 512
    float* k1_s = yt_s + 512;            // 512
    float* h1_s = k1_s + 512;            // 1024  : [c=256][r=4]
    float* h2_s = h1_s + 1024;           // 1024
    float* p_s  = h2_s + 1024;           // 8192  : split-K partials

    const int tid = threadIdx.x;
    const int r0  = blockIdx.x * RB;

    // Cache W1t into shared memory (float4 copies)
    for (int i = tid; i < 8192; i += NTHR)
        *(float4*)&W1s[i * 4] = *(const float4*)&g_W1t[i * 4];

    // y0 = x0 @ W_in^T + b_in   (one (h, r) per thread)
    {
        int h = tid >> 2, r = tid & 3;
        float acc = __ldg(&b_in[h]);
        #pragma unroll
        for (int d = 0; d < D_IN; d++)
            acc += __ldg(&x0[(r0 + r) * D_IN + d]) * __ldg(&W_in[h * D_IN + d]);
        y_s[h * RB + r] = acc;
    }
    const float dt = (ts[32] - ts[0]) / 20.0f;
    __syncthreads();

    for (int step = 0; step < NSTEP; step++) {
        #pragma unroll 1
        for (int phase = 0; phase < 2; phase++) {
            const float* in_s = phase ? yt_s : y_s;
            const int kt = g_idx[2 * step + phase];

            // ---- Layer 1: K=128, C=256. 64 col-blocks x 8 K-slices (16 k) ----
            {
                int cb = tid & 63, s = tid >> 6;
                const float* wp = W1s + (s * 16) * VF_DIM + cb * 4;
                const float* ap = in_s + (s * 16) * 4;
                unsigned long long acc[4][2];
                #pragma unroll
                for (int r = 0; r < 4; r++) { acc[r][0] = 0ull; acc[r][1] = 0ull; }
                #pragma unroll 4
                for (int k = 0; k < 16; k++) {
                    ulonglong2 w = *(const ulonglong2*)(wp + k * VF_DIM);
                    float4 yv = *(const float4*)(ap + k * 4);
                    unsigned long long yd[4] = {dup2(yv.x), dup2(yv.y), dup2(yv.z), dup2(yv.w)};
                    #pragma unroll
                    for (int r = 0; r < 4; r++) {
                        fma2(acc[r][0], w.x, yd[r]);
                        fma2(acc[r][1], w.y, yd[r]);
                    }
                }
                float v[4][4];
                #pragma unroll
                for (int r = 0; r < 4; r++) {
                    unpk(acc[r][0], v[r][0], v[r][1]);
                    unpk(acc[r][1], v[r][2], v[r][3]);
                }
                float* pp = p_s + (s * 64 + cb) * 16;
                #pragma unroll
                for (int ci = 0; ci < 4; ci++)
                    *(float4*)(pp + ci * 4) =
                        make_float4(v[0][ci], v[1][ci], v[2][ci], v[3][ci]);
            }
            __syncthreads();
            if (tid < 256) {   // combine + bias + relu
                float bb = __ldg(&b1[tid]);
                float4 a = make_float4(bb, bb, bb, bb);
                #pragma unroll
                for (int s = 0; s < 8; s++) {
                    float4 q = *(const float4*)&p_s[s * 1024 + tid * 4];
                    a.x += q.x; a.y += q.y; a.z += q.z; a.w += q.w;
                }
                *(float4*)&h1_s[tid * 4] =
                    make_float4(fmaxf(a.x, 0.f), fmaxf(a.y, 0.f),
                                fmaxf(a.z, 0.f), fmaxf(a.w, 0.f));
            }
            __syncthreads();

            // ---- Layer 2: K=256, C=256. 64 col-blocks x 8 K-slices (32 k) ----
            {
                int cb = tid & 63, s = tid >> 6;
                const float* wp = g_W2t + (s * 32) * VF_DIM + cb * 4;
                const float* ap = h1_s + (s * 32) * 4;
                unsigned long long acc[4][2];
                #pragma unroll
                for (int r = 0; r < 4; r++) { acc[r][0] = 0ull; acc[r][1] = 0ull; }
                #pragma unroll 4
                for (int k = 0; k < 32; k++) {
                    ulonglong2 w = *(const ulonglong2*)(wp + k * VF_DIM);
                    float4 yv = *(const float4*)(ap + k * 4);
                    unsigned long long yd[4] = {dup2(yv.x), dup2(yv.y), dup2(yv.z), dup2(yv.w)};
                    #pragma unroll
                    for (int r = 0; r < 4; r++) {
                        fma2(acc[r][0], w.x, yd[r]);
                        fma2(acc[r][1], w.y, yd[r]);
                    }
                }
                float v[4][4];
                #pragma unroll
                for (int r = 0; r < 4; r++) {
                    unpk(acc[r][0], v[r][0], v[r][1]);
                    unpk(acc[r][1], v[r][2], v[r][3]);
                }
                float* pp = p_s + (s * 64 + cb) * 16;
                #pragma unroll
                for (int ci = 0; ci < 4; ci++)
                    *(float4*)(pp + ci * 4) =
                        make_float4(v[0][ci], v[1][ci], v[2][ci], v[3][ci]);
            }
            __syncthreads();
            if (tid < 256) {   // combine + bias + tanh
                float bb = __ldg(&b2[tid]);
                float4 a = make_float4(bb, bb, bb, bb);
                #pragma unroll
                for (int s = 0; s < 8; s++) {
                    float4 q = *(const float4*)&p_s[s * 1024 + tid * 4];
                    a.x += q.x; a.y += q.y; a.z += q.z; a.w += q.w;
                }
                *(float4*)&h2_s[tid * 4] =
                    make_float4(tanhf(a.x), tanhf(a.y), tanhf(a.z), tanhf(a.w));
            }
            __syncthreads();

            // ---- Layer 3: K=256, C=128. 32 col-blocks x 16 K-slices (16 k) ----
            {
                int cb = tid & 31, s = tid >> 5;
                const float* wp = g_Wm + kt * (VF_DIM * H_DIM) + (s * 16) * H_DIM + cb * 4;
                const float* ap = h2_s + (s * 16) * 4;
                unsigned long long acc[4][2];
                #pragma unroll
                for (int r = 0; r < 4; r++) { acc[r][0] = 0ull; acc[r][1] = 0ull; }
                #pragma unroll 4
                for (int k = 0; k < 16; k++) {
                    ulonglong2 w = *(const ulonglong2*)(wp + k * H_DIM);
                    float4 yv = *(const float4*)(ap + k * 4);
                    unsigned long long yd[4] = {dup2(yv.x), dup2(yv.y), dup2(yv.z), dup2(yv.w)};
                    #pragma unroll
                    for (int r = 0; r < 4; r++) {
                        fma2(acc[r][0], w.x, yd[r]);
                        fma2(acc[r][1], w.y, yd[r]);
                    }
                }
                float v[4][4];
                #pragma unroll
                for (int r = 0; r < 4; r++) {
                    unpk(acc[r][0], v[r][0], v[r][1]);
                    unpk(acc[r][1], v[r][2], v[r][3]);
                }
                float* pp = p_s + (s * 32 + cb) * 16;
                #pragma unroll
                for (int ci = 0; ci < 4; ci++)
                    *(float4*)(pp + ci * 4) =
                        make_float4(v[0][ci], v[1][ci], v[2][ci], v[3][ci]);
            }
            __syncthreads();
            if (tid < 128) {   // combine + bias + /delta + Heun update
                int h = tid;
                float4 a = make_float4(0.f, 0.f, 0.f, 0.f);
                #pragma unroll
                for (int s = 0; s < 16; s++) {
                    float4 q = *(const float4*)&p_s[s * 512 + h * 4];
                    a.x += q.x; a.y += q.y; a.z += q.z; a.w += q.w;
                }
                float dl = g_delta[kt];
                float bmv = g_bm[kt * H_DIM + h];
                float d0 = (a.x + bmv) / dl;
                float d1 = (a.y + bmv) / dl;
                float d2 = (a.z + bmv) / dl;
                float d3 = (a.w + bmv) / dl;
                int base = h * RB;
                if (phase == 0) {
                    k1_s[base + 0] = d0; k1_s[base + 1] = d1;
                    k1_s[base + 2] = d2; k1_s[base + 3] = d3;
                    yt_s[base + 0] = y_s[base + 0] + dt * d0;
                    yt_s[base + 1] = y_s[base + 1] + dt * d1;
                    yt_s[base + 2] = y_s[base + 2] + dt * d2;
                    yt_s[base + 3] = y_s[base + 3] + dt * d3;
                } else {
                    y_s[base + 0] = y_s[base + 0] + 0.5f * dt * (k1_s[base + 0] + d0);
                    y_s[base + 1] = y_s[base + 1] + 0.5f * dt * (k1_s[base + 1] + d1);
                    y_s[base + 2] = y_s[base + 2] + 0.5f * dt * (k1_s[base + 2] + d2);
                    y_s[base + 3] = y_s[base + 3] + 0.5f * dt * (k1_s[base + 3] + d3);
                }
            }
            __syncthreads();
        }
    }

    // ---- Output: softmax(y @ W_out^T + b_out), 4 rows x 10 labels ----
    if (tid < RB * LAB) {
        int lab = tid % LAB, r = tid / LAB;
        float acc = __ldg(&b_out[lab]);
        for (int k = 0; k < H_DIM; k++)
            acc += y_s[k * RB + r] * __ldg(&W_out[lab * H_DIM + k]);
        h1_s[r * LAB + lab] = acc;
    }
    __syncthreads();
    if (tid < RB) {
        int r = tid;
        float mx = -1e30f;
        #pragma unroll
        for (int l = 0; l < LAB; l++) mx = fmaxf(mx, h1_s[r * LAB + l]);
        float e[LAB]; float s = 0.f;
        #pragma unroll
        for (int l = 0; l < LAB; l++) { e[l] = expf(h1_s[r * LAB + l] - mx); s += e[l]; }
        #pragma unroll
        for (int l = 0; l < LAB; l++) out[(r0 + r) * LAB + l] = e[l] / s;
    }
}

// ---------------------------------------------------------------------------
extern "C" void kernel_launch(void* const* d_in, const int* in_sizes, int n_in,
                              void* d_out, int out_size)
{
    const float* ts        = (const float*)d_in[0];
    const float* logsig    = (const float*)d_in[1];
    const float* x0        = (const float*)d_in[2];
    const float* intervals = (const float*)d_in[3];
    const float* W_vf1     = (const float*)d_in[4];
    const float* b_vf1     = (const float*)d_in[5];
    const float* W_vf2     = (const float*)d_in[6];
    const float* b_vf2     = (const float*)d_in[7];
    const float* W_m       = (const float*)d_in[8];
    const float* b_m       = (const float*)d_in[9];
    const float* W_in      = (const float*)d_in[10];
    const float* b_in      = (const float*)d_in[11];
    const float* W_out     = (const float*)d_in[12];
    const float* b_out     = (const float*)d_in[13];
    float* out = (float*)d_out;

    size_t smem_bytes = SMEM_FLOATS * sizeof(float);  // 178176 B
    cudaFuncSetAttribute(integrate_kernel,
                         cudaFuncAttributeMaxDynamicSharedMemorySize,
                         (int)smem_bytes);

    setup_kernel<<<160, 256>>>(ts, intervals, W_vf1, W_vf2, logsig, W_m, b_m);
    integrate_kernel<<<NCTA, NTHR, smem_bytes>>>(x0, W_in, b_in, b_vf1, b_vf2,
                                                 W_out, b_out, ts, out);
}

// round 7
// speedup vs baseline: 3.0581x; 1.1561x over previous
#include <cuda_runtime.h>
#include <cuda_bf16.h>
#include <math.h>

// Dimensions (fixed by the problem)
#define B_ROWS 512
#define D_IN 5
#define H_DIM 128
#define VF_DIM 256
#define L_SEG 62        // LS-1
#define LAB 10
#define NSTEP 20
#define RB 4            // rows per CTA
#define NCTA (B_ROWS / RB)   // 128
#define NTHR 512

typedef unsigned long long ull_t;

// Precomputed global scratch (device globals: no allocation allowed)
__device__ float g_W1t[H_DIM * VF_DIM];          // [k=128][c=256]
__device__ float g_W2t[VF_DIM * VF_DIM];         // [k=256][c=256]
__device__ float g_Wm[32 * VF_DIM * H_DIM];      // [idx][v=256][h=128]  4 MB
__device__ float g_bm[32 * H_DIM];               // [idx][h]
__device__ float g_delta[32];                    // interval widths
__device__ int   g_idx[2 * NSTEP];               // 0-based logsig row per eval

// ---------------------------------------------------------------------------
// f32x2 packed-FMA helpers (sm_103a FFMA2 — PTX-only)
// ---------------------------------------------------------------------------
__device__ __forceinline__ ull_t dup2(float x) {
    ull_t r;
    unsigned int u = __float_as_uint(x);
    asm("mov.b64 %0, {%1, %1};" : "=l"(r) : "r"(u));
    return r;
}
__device__ __forceinline__ void fma2(ull_t& acc, ull_t a, ull_t b) {
    asm("fma.rn.f32x2 %0, %1, %2, %0;" : "+l"(acc) : "l"(a), "l"(b));
}
__device__ __forceinline__ void unpk(ull_t v, float& a, float& b) {
    unsigned int lo, hi;
    asm("mov.b64 {%0, %1}, %2;" : "=r"(lo), "=r"(hi) : "l"(v));
    a = __uint_as_float(lo);
    b = __uint_as_float(hi);
}
// split a packed f32x2 (two weights) into two broadcast f32x2 values
__device__ __forceinline__ void dupsplit(ull_t w, ull_t& d0, ull_t& d1) {
    unsigned int lo, hi;
    asm("mov.b64 {%0, %1}, %2;" : "=r"(lo), "=r"(hi) : "l"(w));
    asm("mov.b64 %0, {%1, %1};" : "=l"(d0) : "r"(lo));
    asm("mov.b64 %0, {%1, %1};" : "=l"(d1) : "r"(hi));
}

// ---------------------------------------------------------------------------
// Setup kernel (merged prep + wmeff).  grid = 160 x 256.
// ---------------------------------------------------------------------------
__global__ void __launch_bounds__(256) setup_kernel(
    const float* __restrict__ ts,
    const float* __restrict__ intervals,
    const float* __restrict__ W1,      // [256][128]
    const float* __restrict__ W2,      // [256][256]
    const float* __restrict__ logsig,  // [32][63]
    const float* __restrict__ Wm,      // [7936][256]
    const float* __restrict__ bm)      // [7936]
{
    if (blockIdx.x < 128) {
        __shared__ float ls[32 * L_SEG];
        int h = blockIdx.x;
        int v = threadIdx.x;

        for (int i = threadIdx.x; i < 32 * L_SEG; i += blockDim.x) {
            int row = i / L_SEG, l = i % L_SEG;
            ls[i] = logsig[row * 63 + l + 1];
        }
        __syncthreads();

        float acc[32];
        #pragma unroll
        for (int i = 0; i < 32; i++) acc[i] = 0.0f;

        for (int l = 0; l < L_SEG; l++) {
            float w = __ldg(&Wm[(h * L_SEG + l) * VF_DIM + v]);
            #pragma unroll
            for (int i = 0; i < 32; i++) acc[i] += w * ls[i * L_SEG + l];
        }
        #pragma unroll
        for (int i = 0; i < 32; i++)
            g_Wm[i * (VF_DIM * H_DIM) + v * H_DIM + h] = acc[i];

        if (threadIdx.x < 32) {
            int i = threadIdx.x;
            float s = 0.0f;
            for (int l = 0; l < L_SEG; l++)
                s += __ldg(&bm[h * L_SEG + l]) * ls[i * L_SEG + l];
            g_bm[i * H_DIM + h] = s;
        }
    } else {
        int b = blockIdx.x - 128;              // 0..31
        int gtid = b * 256 + threadIdx.x;      // 0..8191
        int gsz  = 32 * 256;

        for (int i = gtid; i < H_DIM * VF_DIM; i += gsz) {
            int k = i >> 8, c = i & 255;
            g_W1t[i] = W1[c * H_DIM + k];
        }
        for (int i = gtid; i < VF_DIM * VF_DIM; i += gsz) {
            int k = i >> 8, c = i & 255;
            g_W2t[i] = W2[c * VF_DIM + k];
        }
        if (b == 0) {
            if (threadIdx.x < 32)
                g_delta[threadIdx.x] = intervals[threadIdx.x + 1] - intervals[threadIdx.x];
            if (threadIdx.x < 2 * NSTEP) {
                // Replicate reference fp32 exactly
                float t0 = ts[0];
                float dt = (ts[32] - t0) / 20.0f;
                int i = threadIdx.x >> 1;
                float t = t0 + (float)i * dt;
                if (threadIdx.x & 1) t = t + dt;
                int cnt = 0;
                #pragma unroll
                for (int j = 1; j <= 32; j++) cnt += (intervals[j] < t) ? 1 : 0;
                int idx = cnt + 1;
                idx = max(1, min(idx, 32));
                g_idx[threadIdx.x] = idx - 1;
            }
        }
    }
}

// ---------------------------------------------------------------------------
// Persistent integration kernel: 128 CTAs x 512 threads, 4 rows per CTA.
// Software-pipelined GEMMs with cross-phase weight prefetch.
// ---------------------------------------------------------------------------
#define SMEM_FLOATS (32768 + 512 + 512 + 512 + 1024 + 1024 + 8192)  // 178 KB

__global__ void __launch_bounds__(NTHR, 1)
integrate_kernel(const float* __restrict__ x0,     // [512][5]
                 const float* __restrict__ W_in,   // [128][5]
                 const float* __restrict__ b_in,   // [128]
                 const float* __restrict__ b1,     // [256]
                 const float* __restrict__ b2,     // [256]
                 const float* __restrict__ W_out,  // [10][128]
                 const float* __restrict__ b_out,  // [10]
                 const float* __restrict__ ts,
                 float* __restrict__ out)          // [512][10]
{
    extern __shared__ __align__(16) float sm[];
    float* W1s  = sm;                    // 32768 : W1t cached [k][c]
    float* y_s  = W1s + 32768;           // 512   : y   [h=128][r=4]
    float* yt_s = y_s + 512;             // 512
    float* k1_s = yt_s + 512;            // 512
    float* h1_s = k1_s + 512;            // 1024  : [c=256][r=4]
    float* h2_s = h1_s + 1024;           // 1024
    float* p_s  = h2_s + 1024;           // 8192  : split-K partials

    const int tid = threadIdx.x;
    const int r0  = blockIdx.x * RB;
    const int cb  = tid & 63;            // column block
    const int s   = tid >> 6;            // K-slice (0..7)

    // Cache W1t into shared memory (float4 copies)
    for (int i = tid; i < 8192; i += NTHR)
        *(float4*)&W1s[i * 4] = *(const float4*)&g_W1t[i * 4];

    // y0 = x0 @ W_in^T + b_in   (one (h, r) per thread)
    {
        int h = tid >> 2, r = tid & 3;
        float acc = __ldg(&b_in[h]);
        #pragma unroll
        for (int d = 0; d < D_IN; d++)
            acc += __ldg(&x0[(r0 + r) * D_IN + d]) * __ldg(&W_in[h * D_IN + d]);
        y_s[h * RB + r] = acc;
    }
    const float dt = (ts[32] - ts[0]) / 20.0f;
    __syncthreads();

    // Fixed per-thread weight base pointers
    const float* wp1 = W1s   + (s * 16) * VF_DIM + cb * 4;   // layer1, smem
    const float* wp2 = g_W2t + (s * 32) * VF_DIM + cb * 4;   // layer2, global

    for (int step = 0; step < NSTEP; step++) {
        #pragma unroll 1
        for (int phase = 0; phase < 2; phase++) {
            const float* in_s = phase ? yt_s : y_s;
            const int kt = g_idx[2 * step + phase];
            const float* wp3 = g_Wm + kt * (VF_DIM * H_DIM) + (s * 32) * H_DIM + cb * 2;

            ulonglong2 w2buf[4];
            ull_t      w3buf[4];

            // ==== Layer 1 GEMM: K=128, 8 slices x 16 iters, smem weights ====
            {
                const float* ap = in_s + (s * 16) * 4;
                ull_t acc[4][2];
                #pragma unroll
                for (int r = 0; r < 4; r++) { acc[r][0] = 0ull; acc[r][1] = 0ull; }
                #pragma unroll
                for (int k = 0; k < 16; k++) {
                    ulonglong2 w = *(const ulonglong2*)(wp1 + k * VF_DIM);
                    float4 yv = *(const float4*)(ap + k * 4);
                    ull_t yd0 = dup2(yv.x), yd1 = dup2(yv.y), yd2 = dup2(yv.z), yd3 = dup2(yv.w);
                    fma2(acc[0][0], w.x, yd0); fma2(acc[0][1], w.y, yd0);
                    fma2(acc[1][0], w.x, yd1); fma2(acc[1][1], w.y, yd1);
                    fma2(acc[2][0], w.x, yd2); fma2(acc[2][1], w.y, yd2);
                    fma2(acc[3][0], w.x, yd3); fma2(acc[3][1], w.y, yd3);
                }
                float v[4][4];
                #pragma unroll
                for (int r = 0; r < 4; r++) {
                    unpk(acc[r][0], v[r][0], v[r][1]);
                    unpk(acc[r][1], v[r][2], v[r][3]);
                }
                float* pp = p_s + (s * 64 + cb) * 16;
                #pragma unroll
                for (int ci = 0; ci < 4; ci++)
                    *(float4*)(pp + ci * 4) =
                        make_float4(v[0][ci], v[1][ci], v[2][ci], v[3][ci]);
            }
            // Prefetch layer-2 weights (L2 latency hides behind barrier+reduce)
            #pragma unroll
            for (int j = 0; j < 4; j++)
                w2buf[j] = *(const ulonglong2*)(wp2 + j * VF_DIM);
            __syncthreads();

            // ==== Reduce 1 (full width): bias + relu -> h1_s ====
            {
                int c = tid >> 1, hf = (tid & 1) * 2;
                float a0 = 0.f, a1 = 0.f;
                #pragma unroll
                for (int ss = 0; ss < 8; ss++) {
                    float2 q = *(const float2*)&p_s[ss * 1024 + c * 4 + hf];
                    a0 += q.x; a1 += q.y;
                }
                float bb = __ldg(&b1[c]);
                a0 = fmaxf(a0 + bb, 0.f); a1 = fmaxf(a1 + bb, 0.f);
                *(float2*)&h1_s[c * 4 + hf] = make_float2(a0, a1);
            }
            __syncthreads();

            // ==== Layer 2 GEMM: K=256, 8 slices x 32 iters, pipelined ====
            {
                const float* ap = h1_s + (s * 32) * 4;
                float4 abuf[4];
                #pragma unroll
                for (int j = 0; j < 4; j++) abuf[j] = *(const float4*)(ap + j * 4);
                ull_t acc[4][2];
                #pragma unroll
                for (int r = 0; r < 4; r++) { acc[r][0] = 0ull; acc[r][1] = 0ull; }
                #pragma unroll
                for (int kb = 0; kb < 32; kb += 4) {
                    #pragma unroll
                    for (int j = 0; j < 4; j++) {
                        ulonglong2 wn = w2buf[j];
                        float4 an = abuf[j];
                        int nk = kb + 4 + j;
                        if (nk < 32) {                 // compile-time resolved
                            wn = *(const ulonglong2*)(wp2 + nk * VF_DIM);
                            an = *(const float4*)(ap + nk * 4);
                        }
                        ulonglong2 w = w2buf[j];
                        float4 yv = abuf[j];
                        ull_t yd0 = dup2(yv.x), yd1 = dup2(yv.y), yd2 = dup2(yv.z), yd3 = dup2(yv.w);
                        fma2(acc[0][0], w.x, yd0); fma2(acc[0][1], w.y, yd0);
                        fma2(acc[1][0], w.x, yd1); fma2(acc[1][1], w.y, yd1);
                        fma2(acc[2][0], w.x, yd2); fma2(acc[2][1], w.y, yd2);
                        fma2(acc[3][0], w.x, yd3); fma2(acc[3][1], w.y, yd3);
                        w2buf[j] = wn; abuf[j] = an;
                    }
                }
                float v[4][4];
                #pragma unroll
                for (int r = 0; r < 4; r++) {
                    unpk(acc[r][0], v[r][0], v[r][1]);
                    unpk(acc[r][1], v[r][2], v[r][3]);
                }
                float* pp = p_s + (s * 64 + cb) * 16;
                #pragma unroll
                for (int ci = 0; ci < 4; ci++)
                    *(float4*)(pp + ci * 4) =
                        make_float4(v[0][ci], v[1][ci], v[2][ci], v[3][ci]);
            }
            // Prefetch layer-3 weights
            #pragma unroll
            for (int j = 0; j < 4; j++)
                w3buf[j] = *(const ull_t*)(wp3 + j * H_DIM);
            __syncthreads();

            // ==== Reduce 2 (full width): bias + tanh -> h2_s ====
            {
                int c = tid >> 1, hf = (tid & 1) * 2;
                float a0 = 0.f, a1 = 0.f;
                #pragma unroll
                for (int ss = 0; ss < 8; ss++) {
                    float2 q = *(const float2*)&p_s[ss * 1024 + c * 4 + hf];
                    a0 += q.x; a1 += q.y;
                }
                float bb = __ldg(&b2[c]);
                *(float2*)&h2_s[c * 4 + hf] = make_float2(tanhf(a0 + bb), tanhf(a1 + bb));
            }
            __syncthreads();

            // ==== Layer 3 GEMM: C=128, 2 cols x 4 rows, 8 slices x 32 iters ====
            {
                const float* ap = h2_s + (s * 32) * 4;
                ull_t acc[2][2];   // [col][row-pair]
                acc[0][0] = 0ull; acc[0][1] = 0ull;
                acc[1][0] = 0ull; acc[1][1] = 0ull;
                #pragma unroll
                for (int kb = 0; kb < 32; kb += 4) {
                    #pragma unroll
                    for (int j = 0; j < 4; j++) {
                        ull_t wn = w3buf[j];
                        int nk = kb + 4 + j;
                        if (nk < 32)
                            wn = *(const ull_t*)(wp3 + nk * H_DIM);
                        ull_t w = w3buf[j];
                        ulonglong2 av = *(const ulonglong2*)(ap + (kb + j) * 4);
                        ull_t d0, d1;
                        dupsplit(w, d0, d1);
                        fma2(acc[0][0], d0, av.x); fma2(acc[0][1], d0, av.y);
                        fma2(acc[1][0], d1, av.x); fma2(acc[1][1], d1, av.y);
                        w3buf[j] = wn;
                    }
                }
                #pragma unroll
                for (int c = 0; c < 2; c++) {
                    float v0, v1, v2, v3;
                    unpk(acc[c][0], v0, v1);
                    unpk(acc[c][1], v2, v3);
                    *(float4*)&p_s[s * 512 + (cb * 2 + c) * 4] =
                        make_float4(v0, v1, v2, v3);
                }
            }
            __syncthreads();

            // ==== Reduce 3 + Heun (full width, scalar per (h, r)) ====
            {
                int h = tid >> 2, r = tid & 3;
                float a = 0.f;
                #pragma unroll
                for (int ss = 0; ss < 8; ss++)
                    a += p_s[ss * 512 + h * 4 + r];
                float dl  = g_delta[kt];
                float bmv = g_bm[kt * H_DIM + h];
                float d = (a + bmv) / dl;
                int base = h * RB + r;
                if (phase == 0) {
                    k1_s[base] = d;
                    yt_s[base] = y_s[base] + dt * d;
                } else {
                    y_s[base] = y_s[base] + 0.5f * dt * (k1_s[base] + d);
                }
            }
            __syncthreads();
        }
    }

    // ---- Output: softmax(y @ W_out^T + b_out), 4 rows x 10 labels ----
    if (tid < RB * LAB) {
        int lab = tid % LAB, r = tid / LAB;
        float acc = __ldg(&b_out[lab]);
        for (int k = 0; k < H_DIM; k++)
            acc += y_s[k * RB + r] * __ldg(&W_out[lab * H_DIM + k]);
        h1_s[r * LAB + lab] = acc;
    }
    __syncthreads();
    if (tid < RB) {
        int r = tid;
        float mx = -1e30f;
        #pragma unroll
        for (int l = 0; l < LAB; l++) mx = fmaxf(mx, h1_s[r * LAB + l]);
        float e[LAB]; float sum = 0.f;
        #pragma unroll
        for (int l = 0; l < LAB; l++) { e[l] = expf(h1_s[r * LAB + l] - mx); sum += e[l]; }
        #pragma unroll
        for (int l = 0; l < LAB; l++) out[(r0 + r) * LAB + l] = e[l] / sum;
    }
}

// ---------------------------------------------------------------------------
extern "C" void kernel_launch(void* const* d_in, const int* in_sizes, int n_in,
                              void* d_out, int out_size)
{
    const float* ts        = (const float*)d_in[0];
    const float* logsig    = (const float*)d_in[1];
    const float* x0        = (const float*)d_in[2];
    const float* intervals = (const float*)d_in[3];
    const float* W_vf1     = (const float*)d_in[4];
    const float* b_vf1     = (const float*)d_in[5];
    const float* W_vf2     = (const float*)d_in[6];
    const float* b_vf2     = (const float*)d_in[7];
    const float* W_m       = (const float*)d_in[8];
    const float* b_m       = (const float*)d_in[9];
    const float* W_in      = (const float*)d_in[10];
    const float* b_in      = (const float*)d_in[11];
    const float* W_out     = (const float*)d_in[12];
    const float* b_out     = (const float*)d_in[13];
    float* out = (float*)d_out;

    size_t smem_bytes = SMEM_FLOATS * sizeof(float);  // 178176 B
    cudaFuncSetAttribute(integrate_kernel,
                         cudaFuncAttributeMaxDynamicSharedMemorySize,
                         (int)smem_bytes);

    setup_kernel<<<160, 256>>>(ts, intervals, W_vf1, W_vf2, logsig, W_m, b_m);
    integrate_kernel<<<NCTA, NTHR, smem_bytes>>>(x0, W_in, b_in, b_vf1, b_vf2,
                                                 W_out, b_out, ts, out);
}